// round 9
// baseline (speedup 1.0000x reference)
#include <cuda_runtime.h>

typedef unsigned long long ull;
#define IMG (512 * 512)

__device__ __forceinline__ ull pk(float lo, float hi) {
    ull r;
    asm("mov.b64 %0, {%1,%2};" : "=l"(r) : "f"(lo), "f"(hi));
    return r;
}
__device__ __forceinline__ ull ffma2(ull a, ull b, ull c) {
    ull d;
    asm("fma.rn.f32x2 %0, %1, %2, %3;" : "=l"(d) : "l"(a), "l"(b), "l"(c));
    return d;
}
__device__ __forceinline__ ull fadd2(ull a, ull b) {
    ull d;
    asm("add.rn.f32x2 %0, %1, %2;" : "=l"(d) : "l"(a), "l"(b));
    return d;
}
// (a.hi, b.lo)
__device__ __forceinline__ ull cross(ull a, ull b) {
    ull r;
    asm("{\n\t"
        ".reg .b32 al, ah, bl, bh;\n\t"
        "mov.b64 {al, ah}, %1;\n\t"
        "mov.b64 {bl, bh}, %2;\n\t"
        "mov.b64 %0, {ah, bl};\n\t"
        "}" : "=l"(r) : "l"(a), "l"(b));
    return r;
}

// accumulate one step: F += w1*q, P += w0*q, R += w2*q over 9 tap-rows
#define ACC9(TSEL, FV, PV, RV) \
    _Pragma("unroll") \
    for (int tr = 0; tr < 9; tr++) { \
        FV = ffma2(w1p[tr], t[tr].TSEL, FV); \
        PV = ffma2(w0p[tr], t[tr].TSEL, PV); \
        RV = ffma2(w2p[tr], t[tr].TSEL, RV); \
    }

__global__ void __launch_bounds__(128, 3) conv_lane(
    const float* __restrict__ x,   // [8,3,512,512]
    const float* __restrict__ ei,  // [8,192]
    const float* __restrict__ wm,  // [64,3,3,3]
    const float* __restrict__ bm,  // [64]
    const float* __restrict__ we,  // [64,3,3,3]
    const float* __restrict__ be,  // [64]
    float* __restrict__ out)       // [8,64,512,512]
{
    // per-warp transpose buffer: 32 channel-rows x 32 pixel-pair slots (+2 pad)
    __shared__ __align__(16) ull tbuf[4][32][34];

    const int tid = threadIdx.x, lane = tid & 31, wid = tid >> 5;
    const int b = blockIdx.y;
    const int r = blockIdx.x * 2 + (wid >> 1);   // output row
    const int chalf = wid & 1;
    const int c = chalf * 32 + lane;             // this lane's channel

    // ---- channel weights -> registers, once per kernel (zero edge dy rows) ----
    ull w0p[9], w1p[9], w2p[9];
    #pragma unroll
    for (int tr = 0; tr < 9; tr++) {
        int ci = tr / 3, dy = tr % 3;
        float a0 = __ldg(wm + c * 27 + ci * 9 + dy * 3 + 0);
        float a1 = __ldg(wm + c * 27 + ci * 9 + dy * 3 + 1);
        float a2 = __ldg(wm + c * 27 + ci * 9 + dy * 3 + 2);
        if ((r == 0 && dy == 0) || (r == 511 && dy == 2)) { a0 = 0.f; a1 = 0.f; a2 = 0.f; }
        w0p[tr] = pk(a0, a0); w1p[tr] = pk(a1, a1); w2p[tr] = pk(a2, a2);
    }

    // ---- extra-term scalars for this lane's channel ----
    float S = 0, rT = 0, rB = 0, kL = 0, kR = 0;
    float tTL = 0, tTR = 0, tBL = 0, tBR = 0;
    #pragma unroll
    for (int e = 0; e < 3; e++) {
        float v = __ldg(ei + b * 192 + c * 3 + e);
        #pragma unroll
        for (int ky = 0; ky < 3; ky++) {
            #pragma unroll
            for (int kx = 0; kx < 3; kx++) {
                float q = v * __ldg(we + (c * 3 + e) * 9 + ky * 3 + kx);
                S += q;
                if (ky == 0) rT += q;
                if (ky == 2) rB += q;
                if (kx == 0) kL += q;
                if (kx == 2) kR += q;
                if (ky == 0 && kx == 0) tTL += q;
                if (ky == 0 && kx == 2) tTR += q;
                if (ky == 2 && kx == 0) tBL += q;
                if (ky == 2 && kx == 2) tBR += q;
            }
        }
    }
    float base = __ldg(bm + c) + __ldg(be + c) + S
               + (r == 0 ? -rT : 0.f) + (r == 511 ? -rB : 0.f);
    const float adjL = -kL + (r == 0 ? tTL : 0.f) + (r == 511 ? tBL : 0.f);
    const float adjR = -kR + (r == 0 ? tTR : 0.f) + (r == 511 ? tBR : 0.f);
    const ull basePair = pk(base, base);

    // ---- 9 clamped row pointers (clamped rows pair with zeroed weights) ----
    const float* rp[9];
    #pragma unroll
    for (int tr = 0; tr < 9; tr++) {
        int ci = tr / 3, dy = tr % 3;
        int ro = (dy == 0) ? (r > 0 ? r - 1 : 0)
               : (dy == 2) ? (r < 511 ? r + 1 : 511) : r;
        rp[tr] = x + ((size_t)(b * 3 + ci)) * IMG + (size_t)ro * 512;
    }

    const size_t outRowOff = ((size_t)(b * 64 + chalf * 32)) * IMG + (size_t)r * 512;

    // ---- prologue: block 0 (pairs 0 and 1) ----
    ull Fp, Pp2, Pp, Rp;
    {
        ulonglong2 t[9];
        #pragma unroll
        for (int tr = 0; tr < 9; tr++)
            t[tr] = *reinterpret_cast<const ulonglong2*>(rp[tr]);
        ull F0 = basePair, P0 = 0ULL, R0 = 0ULL;
        ACC9(x, F0, P0, R0)
        ull F1 = basePair, P1 = 0ULL, R1 = 0ULL;
        ACC9(y, F1, P1, R1)
        ull o = fadd2(fadd2(F0, cross(0ULL, P0)), cross(R0, R1));
        o = fadd2(o, pk(adjL, 0.f));
        tbuf[wid][lane][0] = o;
        Fp = F1; Pp2 = P0; Pp = P1; Rp = R1;
    }

    // ---- main loop: k covers pairs 2k, 2k+1; emits pairs 2k-1, 2k ----
    #pragma unroll 2
    for (int k = 1; k < 128; k++) {
        ulonglong2 t[9];
        #pragma unroll
        for (int tr = 0; tr < 9; tr++)
            t[tr] = *reinterpret_cast<const ulonglong2*>(rp[tr] + 4 * k);

        ull Fa = basePair, Pa = 0ULL, Ra = 0ULL;
        ACC9(x, Fa, Pa, Ra)
        ull o = fadd2(fadd2(Fp, cross(Pp2, Pp)), cross(Rp, Ra));
        tbuf[wid][lane][(2 * k - 1) & 31] = o;

        ull Fb = basePair, Pb = 0ULL, Rb = 0ULL;
        ACC9(y, Fb, Pb, Rb)
        o = fadd2(fadd2(Fa, cross(Pp, Pa)), cross(Ra, Rb));
        tbuf[wid][lane][(2 * k) & 31] = o;

        Fp = Fb; Pp2 = Pa; Pp = Pb; Rp = Rb;

        if ((k & 7) == 0) {
            // flush chunk m = k/8 - 1 (pairs 16m..16m+15, all emitted)
            int m = (k >> 3) - 1;
            __syncwarp();
            int pb = (m & 1) * 16;
            #pragma unroll
            for (int it = 0; it < 8; it++) {
                int cl = it * 4 + (lane >> 3);
                int g = lane & 7;
                ulonglong2 v = *reinterpret_cast<const ulonglong2*>(&tbuf[wid][cl][pb + 2 * g]);
                float* dst = out + outRowOff + (size_t)cl * IMG + m * 32 + 4 * g;
                *reinterpret_cast<ulonglong2*>(dst) = v;
            }
            __syncwarp();
        }
    }

    // ---- epilogue: emit pair 255 (R_256 = 0), flush chunk 15 ----
    {
        ull o = fadd2(fadd2(Fp, cross(Pp2, Pp)), cross(Rp, 0ULL));
        o = fadd2(o, pk(0.f, adjR));
        tbuf[wid][lane][31] = o;
        __syncwarp();
        #pragma unroll
        for (int it = 0; it < 8; it++) {
            int cl = it * 4 + (lane >> 3);
            int g = lane & 7;
            ulonglong2 v = *reinterpret_cast<const ulonglong2*>(&tbuf[wid][cl][16 + 2 * g]);
            float* dst = out + outRowOff + (size_t)cl * IMG + 15 * 32 + 4 * g;
            *reinterpret_cast<ulonglong2*>(dst) = v;
        }
    }
}

extern "C" void kernel_launch(void* const* d_in, const int* in_sizes, int n_in,
                              void* d_out, int out_size)
{
    const float* x  = (const float*)d_in[0];
    const float* ei = (const float*)d_in[1];
    const float* wm = (const float*)d_in[2];
    const float* bm = (const float*)d_in[3];
    const float* we = (const float*)d_in[4];
    const float* be = (const float*)d_in[5];
    float* out = (float*)d_out;

    dim3 grid(256, 8);   // 256 row-pairs x 8 batches = 2048 CTAs
    conv_lane<<<grid, 128>>>(x, ei, wm, bm, we, be, out);
}

// round 10
// speedup vs baseline: 1.5439x; 1.5439x over previous
#include <cuda_runtime.h>

typedef unsigned long long ull;

#define HW 512
#define IMG (512 * 512)

// weight layout per channel: 28 ull slots (224B, 16B-aligned)
//  slots 0..17 : 9 rows x (w0pair, w2pair)  -> 9 LDC.128
//  slots 18..26: w1pair rows 0..8           -> 5 LDC.128
//  slot  27    : pad
__constant__ ull c_wpair[64 * 28];
__device__ ull d_scratch[64 * 28];

__device__ __forceinline__ ull pk(float lo, float hi) {
    ull r;
    asm("mov.b64 %0, {%1,%2};" : "=l"(r) : "f"(lo), "f"(hi));
    return r;
}
__device__ __forceinline__ ull ffma2(ull a, ull b, ull c) {
    ull d;
    asm("fma.rn.f32x2 %0, %1, %2, %3;" : "=l"(d) : "l"(a), "l"(b), "l"(c));
    return d;
}
__device__ __forceinline__ ull fadd2(ull a, ull b) {
    ull d;
    asm("add.rn.f32x2 %0, %1, %2;" : "=l"(d) : "l"(a), "l"(b));
    return d;
}
// (a.hi, b.lo)
__device__ __forceinline__ ull cross(ull a, ull b) {
    ull r;
    asm("{\n\t"
        ".reg .b32 al, ah, bl, bh;\n\t"
        "mov.b64 {al, ah}, %1;\n\t"
        "mov.b64 {bl, bh}, %2;\n\t"
        "mov.b64 %0, {ah, bl};\n\t"
        "}" : "=l"(r) : "l"(a), "l"(b));
    return r;
}

__global__ void prep_weights(const float* __restrict__ wm) {
    int i = blockIdx.x * blockDim.x + threadIdx.x;   // over 64*28 slots
    if (i < 64 * 28) {
        int c = i / 28, s = i - c * 28;
        float v = 0.f;
        if (s < 18) {
            int r = s >> 1, which = s & 1;           // 0 -> w0, 1 -> w2
            v = wm[c * 27 + r * 3 + (which ? 2 : 0)];
        } else if (s < 27) {
            int r = s - 18;
            v = wm[c * 27 + r * 3 + 1];              // w1
        }
        float* sf = (float*)d_scratch;
        sf[i * 2 + 0] = v;
        sf[i * 2 + 1] = v;
    }
}

// F-taps one row for one channel stream
#define TAPF_(R, F0, F1, F2, F3, CWF) { \
    ulonglong2 u = (CWF)[R]; \
    F0 = ffma2(u.x, W[R][0], F0); F1 = ffma2(u.x, W[R][1], F1); \
    F2 = ffma2(u.x, W[R][2], F2); F3 = ffma2(u.x, W[R][3], F3); \
    F0 = ffma2(u.y, W[R][1], F0); F1 = ffma2(u.y, W[R][2], F1); \
    F2 = ffma2(u.y, W[R][3], F2); F3 = ffma2(u.y, W[R][4], F3); }

// E-taps one row for one channel stream
#define TAPE_(R, WP, E0, E1, E2, E3, E4) { \
    E0 = ffma2(WP, W[R][0], E0); E1 = ffma2(WP, W[R][1], E1); \
    E2 = ffma2(WP, W[R][2], E2); E3 = ffma2(WP, W[R][3], E3); \
    E4 = ffma2(WP, W[R][4], E4); }

#define ROWADJ_(C, F0, F1, F2, F3) { \
    float adj = rowc[C]; \
    float aL = adj + (isL ? cornL[C] : 0.f); \
    float aR = adj + (isR ? cornR[C] : 0.f); \
    ull adjp = pk(adj, adj); \
    F0 = fadd2(F0, pk(aL, adj)); F1 = fadd2(F1, adjp); \
    F2 = fadd2(F2, adjp);        F3 = fadd2(F3, pk(adj, aR)); }

#define EMIT_(F0, F1, F2, F3, E0, E1, E2, E3, E4, OP) { \
    ulonglong2 r01, r23; \
    r01.x = fadd2(F0, cross(E0, E1)); \
    r01.y = fadd2(F1, cross(E1, E2)); \
    r23.x = fadd2(F2, cross(E2, E3)); \
    r23.y = fadd2(F3, cross(E3, E4)); \
    *reinterpret_cast<ulonglong2*>(OP)     = r01; \
    *reinterpret_cast<ulonglong2*>(OP + 4) = r23; }

// dual-channel interleaved loop body: channels c (A) and c+32 (B)
#define CHLOOP2(ROWADJ) \
    _Pragma("unroll 1") \
    for (int c = 0; c < 32; c++) { \
        const ulonglong2* cwFa = (const ulonglong2*)(c_wpair + c * 28); \
        const ulonglong2* cwEa = (const ulonglong2*)(c_wpair + c * 28 + 18); \
        const ulonglong2* cwFb = (const ulonglong2*)(c_wpair + (c + 32) * 28); \
        const ulonglong2* cwEb = (const ulonglong2*)(c_wpair + (c + 32) * 28 + 18); \
        ull bpa = sBase[c], bpb = sBase[c + 32]; \
        ull Fa0 = aptr[c], Fa1 = bpa, Fa2 = bpa, Fa3 = dptr[c]; \
        ull Fb0 = aptr[c + 32], Fb1 = bpb, Fb2 = bpb, Fb3 = dptr[c + 32]; \
        ull Ea0 = 0ULL, Ea1 = 0ULL, Ea2 = 0ULL, Ea3 = 0ULL, Ea4 = 0ULL; \
        ull Eb0 = 0ULL, Eb1 = 0ULL, Eb2 = 0ULL, Eb3 = 0ULL, Eb4 = 0ULL; \
        if (ROWADJ) { \
            ROWADJ_(c, Fa0, Fa1, Fa2, Fa3) \
            ROWADJ_(c + 32, Fb0, Fb1, Fb2, Fb3) \
        } \
        TAPF_(0, Fa0, Fa1, Fa2, Fa3, cwFa) TAPF_(0, Fb0, Fb1, Fb2, Fb3, cwFb) \
        TAPF_(1, Fa0, Fa1, Fa2, Fa3, cwFa) TAPF_(1, Fb0, Fb1, Fb2, Fb3, cwFb) \
        TAPF_(2, Fa0, Fa1, Fa2, Fa3, cwFa) TAPF_(2, Fb0, Fb1, Fb2, Fb3, cwFb) \
        TAPF_(3, Fa0, Fa1, Fa2, Fa3, cwFa) TAPF_(3, Fb0, Fb1, Fb2, Fb3, cwFb) \
        TAPF_(4, Fa0, Fa1, Fa2, Fa3, cwFa) TAPF_(4, Fb0, Fb1, Fb2, Fb3, cwFb) \
        TAPF_(5, Fa0, Fa1, Fa2, Fa3, cwFa) TAPF_(5, Fb0, Fb1, Fb2, Fb3, cwFb) \
        TAPF_(6, Fa0, Fa1, Fa2, Fa3, cwFa) TAPF_(6, Fb0, Fb1, Fb2, Fb3, cwFb) \
        TAPF_(7, Fa0, Fa1, Fa2, Fa3, cwFa) TAPF_(7, Fb0, Fb1, Fb2, Fb3, cwFb) \
        TAPF_(8, Fa0, Fa1, Fa2, Fa3, cwFa) TAPF_(8, Fb0, Fb1, Fb2, Fb3, cwFb) \
        { ulonglong2 va = cwEa[0], vb = cwEb[0]; \
          TAPE_(0, va.x, Ea0, Ea1, Ea2, Ea3, Ea4) TAPE_(0, vb.x, Eb0, Eb1, Eb2, Eb3, Eb4) \
          TAPE_(1, va.y, Ea0, Ea1, Ea2, Ea3, Ea4) TAPE_(1, vb.y, Eb0, Eb1, Eb2, Eb3, Eb4) } \
        { ulonglong2 va = cwEa[1], vb = cwEb[1]; \
          TAPE_(2, va.x, Ea0, Ea1, Ea2, Ea3, Ea4) TAPE_(2, vb.x, Eb0, Eb1, Eb2, Eb3, Eb4) \
          TAPE_(3, va.y, Ea0, Ea1, Ea2, Ea3, Ea4) TAPE_(3, vb.y, Eb0, Eb1, Eb2, Eb3, Eb4) } \
        { ulonglong2 va = cwEa[2], vb = cwEb[2]; \
          TAPE_(4, va.x, Ea0, Ea1, Ea2, Ea3, Ea4) TAPE_(4, vb.x, Eb0, Eb1, Eb2, Eb3, Eb4) \
          TAPE_(5, va.y, Ea0, Ea1, Ea2, Ea3, Ea4) TAPE_(5, vb.y, Eb0, Eb1, Eb2, Eb3, Eb4) } \
        { ulonglong2 va = cwEa[3], vb = cwEb[3]; \
          TAPE_(6, va.x, Ea0, Ea1, Ea2, Ea3, Ea4) TAPE_(6, vb.x, Eb0, Eb1, Eb2, Eb3, Eb4) \
          TAPE_(7, va.y, Ea0, Ea1, Ea2, Ea3, Ea4) TAPE_(7, vb.y, Eb0, Eb1, Eb2, Eb3, Eb4) } \
        { ulonglong2 va = cwEa[4], vb = cwEb[4]; \
          TAPE_(8, va.x, Ea0, Ea1, Ea2, Ea3, Ea4) TAPE_(8, vb.x, Eb0, Eb1, Eb2, Eb3, Eb4) } \
        float* opa = outp + (size_t)c * IMG; \
        float* opb = outp + (size_t)(c + 32) * IMG; \
        EMIT_(Fa0, Fa1, Fa2, Fa3, Ea0, Ea1, Ea2, Ea3, Ea4, opa) \
        EMIT_(Fb0, Fb1, Fb2, Fb3, Eb0, Eb1, Eb2, Eb3, Eb4, opb) \
    }

__global__ void __launch_bounds__(128, 3) conv_main(
    const float* __restrict__ x,   // [8,3,512,512]
    const float* __restrict__ ei,  // [8,192]
    const float* __restrict__ bm,  // [64]
    const float* __restrict__ we,  // [64,3,3,3]
    const float* __restrict__ be,  // [64]
    float* __restrict__ out)       // [8,64,512,512]
{
    __shared__ __align__(16) float xs[3][6][260];   // rows h0-1..h0+4, cols w0-1..w0+256
    __shared__ ull sBase[64], sBaseL[64], sBaseR[64];
    __shared__ float sCT[64], sCB[64], sTL[64], sTR[64], sBL[64], sBR[64];

    const int tid = threadIdx.x, lane = tid & 31, wid = tid >> 5;
    const int cx = blockIdx.x, ty = blockIdx.y, b = blockIdx.z;
    const int w0 = cx * 256, h0 = ty * 4;

    // ---- stage input patch (zero padded) ----
    for (int i = tid; i < 3 * 6 * 258; i += 128) {
        int ci = i / 1548;
        int rem = i - ci * 1548;
        int rr = rem / 258, j = rem - rr * 258;
        int gh = h0 - 1 + rr, gw = w0 - 1 + j;
        float v = 0.f;
        if ((unsigned)gh < 512u && (unsigned)gw < 512u)
            v = x[((b * 3 + ci) * HW + gh) * HW + gw];
        xs[ci][rr][j] = v;
    }

    // ---- per-channel extra-term scalars ----
    if (tid < 64) {
        int c = tid;
        float S = 0, rT = 0, rB = 0, kL = 0, kR = 0;
        float tTL = 0, tTR = 0, tBL = 0, tBR = 0;
        #pragma unroll
        for (int e = 0; e < 3; e++) {
            float v = __ldg(ei + b * 192 + c * 3 + e);
            const float* wq = we + (c * 3 + e) * 9;
            #pragma unroll
            for (int ky = 0; ky < 3; ky++) {
                #pragma unroll
                for (int kx = 0; kx < 3; kx++) {
                    float t = v * __ldg(wq + ky * 3 + kx);
                    S += t;
                    if (ky == 0) rT += t;
                    if (ky == 2) rB += t;
                    if (kx == 0) kL += t;
                    if (kx == 2) kR += t;
                    if (ky == 0 && kx == 0) tTL += t;
                    if (ky == 0 && kx == 2) tTR += t;
                    if (ky == 2 && kx == 0) tBL += t;
                    if (ky == 2 && kx == 2) tBR += t;
                }
            }
        }
        float base = __ldg(bm + c) + __ldg(be + c) + S;
        sBase[c]  = pk(base, base);
        sBaseL[c] = pk(base - kL, base);
        sBaseR[c] = pk(base, base - kR);
        sCT[c] = -rT; sCB[c] = -rB;
        sTL[c] = tTL; sTR[c] = tTR; sBL[c] = tBL; sBR[c] = tBR;
    }
    __syncthreads();

    // ---- build 9x5 register window of aligned pairs q0..q4 per (ci,dy) row ----
    ull W[9][5];
    #pragma unroll
    for (int ci = 0; ci < 3; ci++) {
        #pragma unroll
        for (int dy = 0; dy < 3; dy++) {
            const float* p = &xs[ci][wid + dy][lane * 8];
            ulonglong2 q01 = *reinterpret_cast<const ulonglong2*>(p);
            ulonglong2 q23 = *reinterpret_cast<const ulonglong2*>(p + 4);
            ull q4 = *reinterpret_cast<const ull*>(p + 8);
            int r = ci * 3 + dy;
            W[r][0] = q01.x; W[r][1] = q01.y; W[r][2] = q23.x;
            W[r][3] = q23.y; W[r][4] = q4;
        }
    }

    const int h = h0 + wid;
    const bool isL = (cx == 0) && (lane == 0);
    const bool isR = (cx == 1) && (lane == 31);
    const bool top = (h == 0), bot = (h == HW - 1);

    const ull* aptr = isL ? sBaseL : sBase;
    const ull* dptr = isR ? sBaseR : sBase;

    float* outp = out + (((size_t)b * 64) * HW + h) * HW + w0 + lane * 8;

    if (!(top | bot)) {
        const float* rowc = sCT;
        const float* cornL = sTL;
        const float* cornR = sTR;
        (void)rowc; (void)cornL; (void)cornR;
        CHLOOP2(false)
    } else {
        const float* rowc  = top ? sCT : sCB;
        const float* cornL = top ? sTL : sBL;
        const float* cornR = top ? sTR : sBR;
        CHLOOP2(true)
    }
}

extern "C" void kernel_launch(void* const* d_in, const int* in_sizes, int n_in,
                              void* d_out, int out_size)
{
    const float* x  = (const float*)d_in[0];
    const float* ei = (const float*)d_in[1];
    const float* wm = (const float*)d_in[2];
    const float* bm = (const float*)d_in[3];
    const float* we = (const float*)d_in[4];
    const float* be = (const float*)d_in[5];
    float* out = (float*)d_out;

    prep_weights<<<(64 * 28 + 255) / 256, 256>>>(wm);

    void* scratch_ptr = nullptr;
    cudaGetSymbolAddress(&scratch_ptr, d_scratch);
    cudaMemcpyToSymbolAsync(c_wpair, scratch_ptr, sizeof(ull) * 64 * 28, 0,
                            cudaMemcpyDeviceToDevice, 0);

    dim3 grid(2, 128, 8);   // 2 col-blocks x 128 row-blocks x 8 batches = 2048 CTAs
    conv_main<<<grid, 128>>>(x, ei, bm, we, be, out);
}